// round 14
// baseline (speedup 1.0000x reference)
#include <cuda_runtime.h>
#include <cuda_fp16.h>
#include <cstdint>

// ---------------- problem constants ----------------
#define KTOT   3072
#define NOUT   12288
#define MB     64             // batch (GEMM N side)
#define MTILE  32             // output rows per CTA
#define KC     64             // K per chunk
#define NSPLIT 2
#define NCH    24             // chunks per CTA (48 / NSPLIT)
#define NTH    256
#define NTILES (NOUT / MTILE) // 384

// ---- smem layout ----
// B stages : 3 x (64 rows x 128B fp16, SW128) at 0
// scales   : 3 x 256B                          at 24576
// A packed : 2 x (32 rows x 64B int8)          at 25344
#define SM_B(s)   ((uint32_t)(s) * 8192u)
#define SM_S(s)   (24576u + (uint32_t)(s) * 256u)
#define SM_APK(b) (25344u + (uint32_t)(b) * 2048u)
#define SMEM_TOTAL 29440u

// x pre-converted to fp16, k-permuted within every 16-half window so that
// hw kpair q/grp maps to data k = 4q..4q+3 (matches packed-A word order).
__device__ __align__(16) __half g_xh[MB * KTOT];
// split-K partial sums
__device__ __align__(16) float g_part[NSPLIT * MB * NOUT];

__global__ void xconv_kernel(const float* __restrict__ x) {
    int wdx = blockIdx.x * blockDim.x + threadIdx.x;   // window index (16 halves)
    const float* src = x + (size_t)wdx * 16;
    __half h[16];
#pragma unroll
    for (int p = 0; p < 16; p++) {
        int q = (p >> 1) & 3, rr = p & 1, hh = p >> 3;
        h[p] = __float2half(src[4 * q + 2 * hh + rr]);
    }
    uint4* dst = (uint4*)(g_xh + (size_t)wdx * 16);
    dst[0] = *(uint4*)&h[0];
    dst[1] = *(uint4*)&h[8];
}

__global__ void reduce_kernel(const int* __restrict__ bq,
                              const float* __restrict__ bs,
                              float* __restrict__ out) {
    int i = blockIdx.x * blockDim.x + threadIdx.x;     // float4 index
    float4 a = ((const float4*)g_part)[i];
    float4 b = ((const float4*)g_part)[i + (MB * NOUT / 4)];
    int o0 = (i % (NOUT / 4)) * 4;
    int4 q4 = *(const int4*)(bq + o0);
    float s = bs[o0 >> 5];
    float4 r;
    r.x = a.x + b.x + ((float)q4.x - 128.0f) * s;
    r.y = a.y + b.y + ((float)q4.y - 128.0f) * s;
    r.z = a.z + b.z + ((float)q4.z - 128.0f) * s;
    r.w = a.w + b.w + ((float)q4.w - 128.0f) * s;
    ((float4*)out)[i] = r;
}

// ---------------- device helpers ----------------
__device__ __forceinline__ uint32_t smem_u32(const void* p) {
    uint32_t a;
    asm("{ .reg .u64 t; cvta.to.shared.u64 t, %1; cvt.u32.u64 %0, t; }" : "=r"(a) : "l"(p));
    return a;
}
__device__ __forceinline__ uint32_t swz(uint32_t off) {  // SW128 Swizzle<3,4,3>
    return off ^ ((off >> 3) & 0x70u);
}
__device__ __forceinline__ void cp_async16(uint32_t dst, const void* src) {
    asm volatile("cp.async.cg.shared.global [%0], [%1], 16;"
                 :: "r"(dst), "l"(src) : "memory");
}
__device__ __forceinline__ void cp_async8(uint32_t dst, const void* src) {
    asm volatile("cp.async.ca.shared.global [%0], [%1], 8;"
                 :: "r"(dst), "l"(src) : "memory");
}
#define CP_COMMIT()  asm volatile("cp.async.commit_group;" ::: "memory")
#define CP_WAIT(n)   asm volatile("cp.async.wait_group %0;" :: "n"(n) : "memory")

__device__ __forceinline__ void sts32(uint32_t addr, uint32_t v) {
    asm volatile("st.shared.b32 [%0], %1;" :: "r"(addr), "r"(v) : "memory");
}
__device__ __forceinline__ uint32_t lds32(uint32_t addr) {
    uint32_t v;
    asm volatile("ld.shared.b32 %0, [%1];" : "=r"(v) : "r"(addr));
    return v;
}
__device__ __forceinline__ void ldsm4(uint32_t* r, uint32_t addr) {
    asm volatile("ldmatrix.sync.aligned.m8n8.x4.shared.b16 {%0,%1,%2,%3}, [%4];"
                 : "=r"(r[0]), "=r"(r[1]), "=r"(r[2]), "=r"(r[3]) : "r"(addr));
}
__device__ __forceinline__ void mma16816(float* c,
                                         uint32_t a0, uint32_t a1, uint32_t a2, uint32_t a3,
                                         uint32_t b0, uint32_t b1) {
    asm volatile(
        "mma.sync.aligned.m16n8k16.row.col.f32.f16.f16.f32 "
        "{%0,%1,%2,%3}, {%4,%5,%6,%7}, {%8,%9}, {%0,%1,%2,%3};"
        : "+f"(c[0]), "+f"(c[1]), "+f"(c[2]), "+f"(c[3])
        : "r"(a0), "r"(a1), "r"(a2), "r"(a3), "r"(b0), "r"(b1));
}
__device__ __forceinline__ uint32_t pack4(int4 c) {   // low bytes of 4 codes
    uint32_t u = __byte_perm((uint32_t)c.x, (uint32_t)c.y, 0x0040);
    uint32_t v = __byte_perm((uint32_t)c.z, (uint32_t)c.w, 0x0040);
    return __byte_perm(u, v, 0x5410);
}
__device__ __forceinline__ uint32_t dq_h(uint32_t packed, uint32_t sel, __half2 s2) {
    const __half2 c1152 = __half2(__ushort_as_half((unsigned short)0x6480),
                                  __ushort_as_half((unsigned short)0x6480));
    uint32_t h = __byte_perm(packed, 0x64006400u, sel);
    __half2 v = __hmul2(__hsub2(*(__half2*)&h, c1152), s2);
    return *(uint32_t*)&v;
}

__global__ __launch_bounds__(NTH, 5)
void dql_kernel(const int*   __restrict__ wq,
                const float* __restrict__ ws) {
    extern __shared__ __align__(16) char smem[];
    const uint32_t sb = smem_u32(smem);

    const int tid  = threadIdx.x;
    const int lane = tid & 31;
    const int wid  = tid >> 5;
    const int wm   = wid & 1;      // output-row half (16)
    const int wn   = wid >> 1;     // batch quarter (16)
    const int cta  = blockIdx.x;
    const int split = blockIdx.y;
    const int cbase = split * NCH;

    // ---- A producer: LDG raw codes, pack to int8, STS (XOR word layout) ----
    const int a_R = tid >> 3;      // 0..31 (weight row)
    const int a_s = tid & 7;       // 4-code segment (covers segs a_s, a_s+8)
    const int* a_src = wq + (size_t)(cta * MTILE + a_R) * KTOT + a_s * 4 + cbase * KC;
    const uint32_t a_pv = (uint32_t)(((a_R >> 1) & 3) << 2);
    const uint32_t a_w0 = ((uint32_t)a_s       ^ a_pv) * 4;
    const uint32_t a_w1 = ((uint32_t)(a_s + 8) ^ a_pv) * 4;
    const uint32_t a_rowb = (uint32_t)(a_R * 64);

    // ---- B + scales cp.async mapping ----
    const int brow = tid >> 2;     // 0..63 (batch row)
    const int bseg = tid & 3;
    const char* b_src0 = (const char*)(g_xh + (size_t)brow * KTOT) +
                         bseg * 16 + (size_t)cbase * (KC * 2);
    const char* s_src0 = (const char*)(ws + (size_t)(cta * MTILE + tid) * (KTOT / 32)) +
                         (size_t)cbase * 8;
    const uint32_t b_d0 = swz((uint32_t)(brow * 128 + bseg * 16));
    const uint32_t b_d1 = swz((uint32_t)(brow * 128 + (bseg + 4) * 16));

    auto issueB = [&](int c) {
        const uint32_t st = sb + SM_B(c % 3);
        const char* s = b_src0 + (size_t)c * (KC * 2);
        cp_async16(st + b_d0, s);
        cp_async16(st + b_d1, s + 64);
        if (tid < MTILE)
            cp_async8(sb + SM_S(c % 3) + (uint32_t)(tid * 8), s_src0 + (size_t)c * 8);
    };

    int4 ar0, ar1;                 // A LDG staging (one chunk)
    auto ldgA = [&](int c) {
        const int* p = a_src + c * KC;
        ar0 = *(const int4*)(p);
        ar1 = *(const int4*)(p + 32);
    };
    auto stsA = [&](int c) {
        const uint32_t base = sb + SM_APK(c & 1) + a_rowb;
        sts32(base + a_w0, pack4(ar0));
        sts32(base + a_w1, pack4(ar1));
    };

    float acc[2][4];
#pragma unroll
    for (int u = 0; u < 2; u++)
#pragma unroll
        for (int i = 0; i < 4; i++) acc[u][i] = 0.0f;

    // ---- consumer addressing ----
    const int r  = lane >> 2;
    const int q  = lane & 3;
    const int R0 = wm * 16 + r;            // fragment rows R0, R0+8
    const uint32_t pv  = (uint32_t)(((R0 >> 1) & 3) << 2);  // same for R0 and R0+8
    const uint32_t aw0 = (uint32_t)(R0 * 64);
    const uint32_t aw1 = (uint32_t)((R0 + 8) * 64);
    const uint32_t b_lrow = (uint32_t)(wn * 16 + (lane & 7) + ((lane >> 4) & 1) * 8);
    const uint32_t b_hcol = (uint32_t)(((lane >> 3) & 1) * 16);

    // ---- prologue ----
    issueB(0); CP_COMMIT();
    issueB(1); CP_COMMIT();
    ldgA(0); stsA(0);
    ldgA(1);

    for (int c = 0; c < NCH; c++) {
        CP_WAIT(1);                  // B stage c complete
        __syncthreads();             // APK[c&1] visible; slot reuse safe

        if (c + 2 < NCH) issueB(c + 2);
        CP_COMMIT();
        if (c + 1 < NCH) {
            stsA(c + 1);
            if (c + 2 < NCH) ldgA(c + 2);
        }

        const uint32_t APK = sb + SM_APK(c & 1);
        const uint32_t Ss  = sb + SM_S(c % 3);
        const uint32_t Bs  = sb + SM_B(c % 3);

        // per-row scale half2s (block .x for ksteps 0-1, .y for 2-3)
        float2 s0 = *(const float2*)(smem + (Ss - sb) + (uint32_t)(R0 * 8));
        float2 s1 = *(const float2*)(smem + (Ss - sb) + (uint32_t)((R0 + 8) * 8));
        __half2 hs0x = __float2half2_rn(s0.x), hs0y = __float2half2_rn(s0.y);
        __half2 hs1x = __float2half2_rn(s1.x), hs1y = __float2half2_rn(s1.y);

#pragma unroll
        for (int t = 0; t < 4; t++) {
            const uint32_t woff = (((uint32_t)(t * 4 + q)) ^ pv) << 2;
            uint32_t p0 = lds32(APK + aw0 + woff);
            uint32_t p1 = lds32(APK + aw1 + woff);
            const __half2 sA = (t < 2) ? hs0x : hs0y;
            const __half2 sB = (t < 2) ? hs1x : hs1y;
            uint32_t a0 = dq_h(p0, 0x5150, sA);
            uint32_t a1 = dq_h(p1, 0x5150, sB);
            uint32_t a2 = dq_h(p0, 0x5352, sA);
            uint32_t a3 = dq_h(p1, 0x5352, sB);

            uint32_t bt[4];
            ldsm4(bt, Bs + swz(b_lrow * 128 + (uint32_t)(t * 32) + b_hcol));

            mma16816(acc[0], a0, a1, a2, a3, bt[0], bt[1]);
            mma16816(acc[1], a0, a1, a2, a3, bt[2], bt[3]);
        }
    }

    // ---- epilogue: direct STG of partials ----
    {
        float* pb = g_part + (size_t)split * (MB * NOUT);
        const int o  = cta * MTILE + R0;
        const int mb = wn * 16 + q * 2;
#pragma unroll
        for (int u = 0; u < 2; u++) {
            const int m = mb + u * 8;
            pb[(size_t)m * NOUT + o]           = acc[u][0];
            pb[(size_t)(m + 1) * NOUT + o]     = acc[u][1];
            pb[(size_t)m * NOUT + o + 8]       = acc[u][2];
            pb[(size_t)(m + 1) * NOUT + o + 8] = acc[u][3];
        }
    }
}

extern "C" void kernel_launch(void* const* d_in, const int* in_sizes, int n_in,
                              void* d_out, int out_size) {
    (void)in_sizes; (void)n_in; (void)out_size;
    xconv_kernel<<<(MB * KTOT / 16) / NTH, NTH>>>((const float*)d_in[0]);
    cudaFuncSetAttribute(dql_kernel, cudaFuncAttributeMaxDynamicSharedMemorySize, SMEM_TOTAL);
    dql_kernel<<<dim3(NTILES, NSPLIT), NTH, SMEM_TOTAL>>>(
        (const int*)d_in[1],     // w_q
        (const float*)d_in[2]);  // w_scales
    reduce_kernel<<<(MB * NOUT / 4) / NTH, NTH>>>(
        (const int*)d_in[3],     // b_q
        (const float*)d_in[4],   // b_scales
        (float*)d_out);
}